// round 1
// baseline (speedup 1.0000x reference)
#include <cuda_runtime.h>
#include <math.h>

#define N_NODES 20000
#define N_EDGES 320000
#define H 128
#define NRBF 20
#define NATTR 28
#define F48 48            // NATTR + NRBF
#define TILE_E 64
#define NTILES (N_EDGES / TILE_E)   // 5000 exactly

// ---------------- device scratch (no dynamic alloc allowed) ----------------
__device__ float g_P[N_NODES * H];     // h @ ew1[48:176] + eb1   (dst part)
__device__ float g_Q[N_NODES * H];     // h @ ew1[176:304]        (src part)
__device__ float g_mi[N_NODES * H];    // segment_sum(mij*eij)
__device__ float g_xacc[N_NODES * 3];  // segment_sum(rel_x*xg)

// =====================================================================
// Kernel 1: P/Q node pre-GEMMs + zero the accumulators
// grid 625 x 256, each block computes 32 nodes x 128 cols for P and Q
// =====================================================================
__global__ __launch_bounds__(256) void k_pre(
    const float* __restrict__ h,
    const float* __restrict__ ew1,
    const float* __restrict__ eb1)
{
    // zero accumulators (grid-stride)
    for (int i = blockIdx.x * 256 + threadIdx.x; i < N_NODES * H; i += gridDim.x * 256)
        g_mi[i] = 0.f;
    for (int i = blockIdx.x * 256 + threadIdx.x; i < N_NODES * 3; i += gridDim.x * 256)
        g_xacc[i] = 0.f;

    __shared__ float hs[32 * 128];
    __shared__ float ws[32 * 128];

    const int tid = threadIdx.x;
    const int n0  = blockIdx.x * 32;          // 625*32 = 20000 exactly
    const int tx  = tid & 15;                 // col group: cols tx*8 .. tx*8+7
    const int ny  = tid >> 4;                 // node group: nodes 2ny, 2ny+1

    // stage h tile [32][128]
    for (int i = tid; i < 32 * 128 / 4; i += 256)
        ((float4*)hs)[i] = ((const float4*)(h + (size_t)n0 * H))[i];

    for (int part = 0; part < 2; part++) {
        float acc[2][8];
        #pragma unroll
        for (int i = 0; i < 2; i++)
            #pragma unroll
            for (int j = 0; j < 8; j++)
                acc[i][j] = (part == 0) ? eb1[tx * 8 + j] : 0.f;

        const int roff = (part == 0) ? 48 : 176;
        for (int kt = 0; kt < 128; kt += 32) {
            __syncthreads();
            for (int i = tid; i < 32 * 128 / 4; i += 256)
                ((float4*)ws)[i] = ((const float4*)(ew1 + (size_t)(roff + kt) * H))[i];
            __syncthreads();
            #pragma unroll 4
            for (int kk = 0; kk < 32; kk++) {
                float u0 = hs[(2 * ny + 0) * 128 + kt + kk];
                float u1 = hs[(2 * ny + 1) * 128 + kt + kk];
                float w[8];
                *(float4*)&w[0] = *(float4*)&ws[kk * 128 + tx * 8];
                *(float4*)&w[4] = *(float4*)&ws[kk * 128 + tx * 8 + 4];
                #pragma unroll
                for (int j = 0; j < 8; j++) {
                    acc[0][j] += u0 * w[j];
                    acc[1][j] += u1 * w[j];
                }
            }
        }
        float* dst = (part == 0) ? g_P : g_Q;
        #pragma unroll
        for (int i = 0; i < 2; i++) {
            float4 o0 = make_float4(acc[i][0], acc[i][1], acc[i][2], acc[i][3]);
            float4 o1 = make_float4(acc[i][4], acc[i][5], acc[i][6], acc[i][7]);
            *(float4*)&dst[(size_t)(n0 + 2 * ny + i) * H + tx * 8]     = o0;
            *(float4*)&dst[(size_t)(n0 + 2 * ny + i) * H + tx * 8 + 4] = o1;
        }
        __syncthreads();
    }
}

// =====================================================================
// Kernel 2: fused edge kernel (persistent). For each 64-edge tile:
//   u   = relu(P[dst] + Q[src] + f48 @ ew1[0:48])        (eb1 folded in P)
//   mij = relu(u @ ew2 + eb2)
//   eij = sigmoid(mij . inf_w + inf_b)
//   mi[dst]   += mij * eij        (coalesced atomics)
//   v   = relu(mij @ xw1 + xb1);  xg = v . xw2 + xb2
//   xacc[dst] += rel_x * xg
// =====================================================================
__global__ __launch_bounds__(256, 1) void k_edge(
    const float* __restrict__ x,
    const float* __restrict__ edge_attr,
    const float* __restrict__ ew1,
    const float* __restrict__ ew2,
    const float* __restrict__ eb2,
    const float* __restrict__ inf_w,
    const float* __restrict__ inf_b,
    const float* __restrict__ xw1,
    const float* __restrict__ xb1,
    const float* __restrict__ xw2,
    const float* __restrict__ xb2,
    const int* __restrict__ ei)
{
    extern __shared__ float sm[];
    float* ew1s  = sm;                    // 48*128  = 6144
    float* ew2s  = ew1s + 48 * 128;       // 128*128 = 16384
    float* xw1s  = ew2s + 128 * 128;      // 16384
    float* us    = xw1s + 128 * 128;      // 64*132  = 8448
    float* ms    = us + 64 * 132;         // 8448  (f48 aliased inside)
    float* f48s  = ms;                    // 64*49 = 3136 (dead before ms written)
    float* eb2s  = ms + 64 * 132;         // 128
    float* xb1s  = eb2s + 128;            // 128
    float* infws = xb1s + 128;            // 128
    float* xw2s  = infws + 128;           // 128
    float* eijs  = xw2s + 128;            // 64
    float* rels  = eijs + 64;             // 192
    int*   dsts  = (int*)(rels + 192);    // 64
    int*   srcs  = dsts + 64;             // 64

    const int tid = threadIdx.x;

    // load weights into smem (once per block)
    for (int i = tid; i < 48 * 128 / 4; i += 256)  ((float4*)ew1s)[i] = ((const float4*)ew1)[i];
    for (int i = tid; i < 128 * 128 / 4; i += 256) ((float4*)ew2s)[i] = ((const float4*)ew2)[i];
    for (int i = tid; i < 128 * 128 / 4; i += 256) ((float4*)xw1s)[i] = ((const float4*)xw1)[i];
    if (tid < 128) {
        eb2s[tid]  = eb2[tid];
        xb1s[tid]  = xb1[tid];
        infws[tid] = inf_w[tid];
        xw2s[tid]  = xw2[tid];
    }
    const float infb = inf_b[0];
    const float xb2v = xb2[0];

    const int tx = tid & 15;   // cols tx*8 .. tx*8+7
    const int ey = tid >> 4;   // edges ey*4 .. ey*4+3

    const float OFFSTEP = 100.f / 19.f;
    const float COEFF   = -0.5f / (OFFSTEP * OFFSTEP);

    for (int t = blockIdx.x; t < NTILES; t += gridDim.x) {
        const int e0 = t * TILE_E;
        __syncthreads();   // protect smem buffers from previous tile

        // ---- stage edge_attr + rbf + indices + rel_x ----
        for (int i = tid; i < TILE_E * NATTR; i += 256) {
            int e = i / NATTR, k = i - e * NATTR;
            f48s[e * 49 + k] = edge_attr[(size_t)(e0 + e) * NATTR + k];
        }
        if (tid < TILE_E) {
            int e = e0 + tid;
            int d = ei[e], s = ei[N_EDGES + e];
            dsts[tid] = d; srcs[tid] = s;
            float rx = x[d * 3 + 0] - x[s * 3 + 0];
            float ry = x[d * 3 + 1] - x[s * 3 + 1];
            float rz = x[d * 3 + 2] - x[s * 3 + 2];
            rels[tid * 3 + 0] = rx; rels[tid * 3 + 1] = ry; rels[tid * 3 + 2] = rz;
            float l2 = sqrtf(rx * rx + ry * ry + rz * rz);
            #pragma unroll
            for (int k = 0; k < NRBF; k++) {
                float dd = l2 - (float)k * OFFSTEP;
                f48s[tid * 49 + NATTR + k] = expf(COEFF * dd * dd);
            }
        }
        __syncthreads();

        // ---- GEMM1: u = relu(P[dst] + Q[src] + f48 @ ew1[0:48]) ----
        float acc[4][8];
        int ed[4];
        #pragma unroll
        for (int i = 0; i < 4; i++) ed[i] = dsts[ey * 4 + i];
        #pragma unroll
        for (int i = 0; i < 4; i++) {
            int s = srcs[ey * 4 + i];
            const float4* Pp = (const float4*)(g_P + (size_t)ed[i] * H + tx * 8);
            const float4* Qp = (const float4*)(g_Q + (size_t)s * H + tx * 8);
            float4 p0 = Pp[0], p1 = Pp[1];
            float4 q0 = Qp[0], q1 = Qp[1];
            acc[i][0] = p0.x + q0.x; acc[i][1] = p0.y + q0.y;
            acc[i][2] = p0.z + q0.z; acc[i][3] = p0.w + q0.w;
            acc[i][4] = p1.x + q1.x; acc[i][5] = p1.y + q1.y;
            acc[i][6] = p1.z + q1.z; acc[i][7] = p1.w + q1.w;
        }
        #pragma unroll 4
        for (int k = 0; k < F48; k++) {
            float w[8];
            *(float4*)&w[0] = *(float4*)&ew1s[k * 128 + tx * 8];
            *(float4*)&w[4] = *(float4*)&ew1s[k * 128 + tx * 8 + 4];
            float u0 = f48s[(ey * 4 + 0) * 49 + k];
            float u1 = f48s[(ey * 4 + 1) * 49 + k];
            float u2 = f48s[(ey * 4 + 2) * 49 + k];
            float u3 = f48s[(ey * 4 + 3) * 49 + k];
            #pragma unroll
            for (int j = 0; j < 8; j++) {
                acc[0][j] += u0 * w[j];
                acc[1][j] += u1 * w[j];
                acc[2][j] += u2 * w[j];
                acc[3][j] += u3 * w[j];
            }
        }
        #pragma unroll
        for (int i = 0; i < 4; i++) {
            float o[8];
            #pragma unroll
            for (int j = 0; j < 8; j++) o[j] = fmaxf(acc[i][j], 0.f);
            *(float4*)&us[(ey * 4 + i) * 132 + tx * 8]     = *(float4*)&o[0];
            *(float4*)&us[(ey * 4 + i) * 132 + tx * 8 + 4] = *(float4*)&o[4];
        }
        __syncthreads();

        // ---- GEMM2: mij = relu(u @ ew2 + eb2); eij ----
        {
            float b[8];
            *(float4*)&b[0] = *(float4*)&eb2s[tx * 8];
            *(float4*)&b[4] = *(float4*)&eb2s[tx * 8 + 4];
            #pragma unroll
            for (int i = 0; i < 4; i++)
                #pragma unroll
                for (int j = 0; j < 8; j++) acc[i][j] = b[j];
        }
        #pragma unroll 4
        for (int k = 0; k < 128; k++) {
            float w[8];
            *(float4*)&w[0] = *(float4*)&ew2s[k * 128 + tx * 8];
            *(float4*)&w[4] = *(float4*)&ew2s[k * 128 + tx * 8 + 4];
            float u0 = us[(ey * 4 + 0) * 132 + k];
            float u1 = us[(ey * 4 + 1) * 132 + k];
            float u2 = us[(ey * 4 + 2) * 132 + k];
            float u3 = us[(ey * 4 + 3) * 132 + k];
            #pragma unroll
            for (int j = 0; j < 8; j++) {
                acc[0][j] += u0 * w[j];
                acc[1][j] += u1 * w[j];
                acc[2][j] += u2 * w[j];
                acc[3][j] += u3 * w[j];
            }
        }
        float pd[4] = {0.f, 0.f, 0.f, 0.f};
        {
            float wv[8];
            *(float4*)&wv[0] = *(float4*)&infws[tx * 8];
            *(float4*)&wv[4] = *(float4*)&infws[tx * 8 + 4];
            #pragma unroll
            for (int i = 0; i < 4; i++) {
                float o[8];
                #pragma unroll
                for (int j = 0; j < 8; j++) {
                    o[j] = fmaxf(acc[i][j], 0.f);
                    pd[i] += o[j] * wv[j];
                }
                *(float4*)&ms[(ey * 4 + i) * 132 + tx * 8]     = *(float4*)&o[0];
                *(float4*)&ms[(ey * 4 + i) * 132 + tx * 8 + 4] = *(float4*)&o[4];
            }
        }
        #pragma unroll
        for (int o = 8; o >= 1; o >>= 1) {
            #pragma unroll
            for (int i = 0; i < 4; i++)
                pd[i] += __shfl_xor_sync(0xFFFFFFFFu, pd[i], o, 16);
        }
        float eij[4];
        #pragma unroll
        for (int i = 0; i < 4; i++)
            eij[i] = 1.f / (1.f + expf(-(pd[i] + infb)));
        if (tx == 0) {
            #pragma unroll
            for (int i = 0; i < 4; i++) eijs[ey * 4 + i] = eij[i];
        }
        __syncthreads();   // ms + eijs fully visible

        // ---- coalesced scatter: mi[dst] += mij * eij ----
        for (int idx = tid; idx < TILE_E * H; idx += 256) {
            int e = idx >> 7, c = idx & 127;
            atomicAdd(&g_mi[(size_t)dsts[e] * H + c], ms[e * 132 + c] * eijs[e]);
        }

        // ---- GEMM3: v = relu(mij @ xw1 + xb1); xg = v . xw2 + xb2 ----
        {
            float b[8];
            *(float4*)&b[0] = *(float4*)&xb1s[tx * 8];
            *(float4*)&b[4] = *(float4*)&xb1s[tx * 8 + 4];
            #pragma unroll
            for (int i = 0; i < 4; i++)
                #pragma unroll
                for (int j = 0; j < 8; j++) acc[i][j] = b[j];
        }
        #pragma unroll 4
        for (int k = 0; k < 128; k++) {
            float w[8];
            *(float4*)&w[0] = *(float4*)&xw1s[k * 128 + tx * 8];
            *(float4*)&w[4] = *(float4*)&xw1s[k * 128 + tx * 8 + 4];
            float u0 = ms[(ey * 4 + 0) * 132 + k];
            float u1 = ms[(ey * 4 + 1) * 132 + k];
            float u2 = ms[(ey * 4 + 2) * 132 + k];
            float u3 = ms[(ey * 4 + 3) * 132 + k];
            #pragma unroll
            for (int j = 0; j < 8; j++) {
                acc[0][j] += u0 * w[j];
                acc[1][j] += u1 * w[j];
                acc[2][j] += u2 * w[j];
                acc[3][j] += u3 * w[j];
            }
        }
        float pd2[4] = {0.f, 0.f, 0.f, 0.f};
        {
            float wv[8];
            *(float4*)&wv[0] = *(float4*)&xw2s[tx * 8];
            *(float4*)&wv[4] = *(float4*)&xw2s[tx * 8 + 4];
            #pragma unroll
            for (int i = 0; i < 4; i++)
                #pragma unroll
                for (int j = 0; j < 8; j++)
                    pd2[i] += fmaxf(acc[i][j], 0.f) * wv[j];
        }
        #pragma unroll
        for (int o = 8; o >= 1; o >>= 1) {
            #pragma unroll
            for (int i = 0; i < 4; i++)
                pd2[i] += __shfl_xor_sync(0xFFFFFFFFu, pd2[i], o, 16);
        }
        if (tx < 12) {
            int i = tx / 3;
            int c = tx - 3 * i;
            int e = ey * 4 + i;
            float xg = pd2[i] + xb2v;
            atomicAdd(&g_xacc[(size_t)dsts[e] * 3 + c], rels[e * 3 + c] * xg);
        }
    }
}

// =====================================================================
// Kernel 3: node MLP + coordinate write
//   out = relu([mi, h] @ nw1 + nb1) @ nw2 + nb2
//   x_new = x + xacc / E
// =====================================================================
__global__ __launch_bounds__(256, 1) void k_post(
    const float* __restrict__ h,
    const float* __restrict__ x,
    const float* __restrict__ nw1,
    const float* __restrict__ nb1,
    const float* __restrict__ nw2,
    const float* __restrict__ nb2,
    float* __restrict__ out)
{
    extern __shared__ float sm[];
    float* As   = sm;                 // 32*260 = 8320
    float* ws   = As + 32 * 260;      // 64*128 = 8192
    float* ts   = ws + 64 * 128;      // 32*132 = 4224
    float* nw2s = ts + 32 * 132;      // 16384

    const int tid = threadIdx.x;
    const int n0  = blockIdx.x * 32;
    const int tx  = tid & 15;
    const int ny  = tid >> 4;

    // coordinate update (grid covers 625*256 = 160000 >= 60000 elements)
    {
        int i = blockIdx.x * 256 + tid;
        if (i < N_NODES * 3)
            out[(size_t)N_NODES * H + i] = x[i] + g_xacc[i] * (1.f / (float)N_EDGES);
    }

    // stage nw2 and A = [mi | h]
    for (int i = tid; i < 128 * 128 / 4; i += 256)
        ((float4*)nw2s)[i] = ((const float4*)nw2)[i];
    for (int i = tid; i < 32 * 128 / 4; i += 256) {
        int fi = i * 4;
        int n = fi >> 7, c = fi & 127;
        *(float4*)&As[n * 260 + c]       = *(const float4*)&g_mi[(size_t)(n0 + n) * H + c];
        *(float4*)&As[n * 260 + 128 + c] = *(const float4*)&h[(size_t)(n0 + n) * H + c];
    }

    float acc[2][8];
    #pragma unroll
    for (int i = 0; i < 2; i++)
        #pragma unroll
        for (int j = 0; j < 8; j++)
            acc[i][j] = nb1[tx * 8 + j];

    for (int kt = 0; kt < 256; kt += 64) {
        __syncthreads();
        for (int i = tid; i < 64 * 128 / 4; i += 256)
            ((float4*)ws)[i] = ((const float4*)(nw1 + (size_t)kt * H))[i];
        __syncthreads();
        #pragma unroll 4
        for (int kk = 0; kk < 64; kk++) {
            float u0 = As[(2 * ny + 0) * 260 + kt + kk];
            float u1 = As[(2 * ny + 1) * 260 + kt + kk];
            float w[8];
            *(float4*)&w[0] = *(float4*)&ws[kk * 128 + tx * 8];
            *(float4*)&w[4] = *(float4*)&ws[kk * 128 + tx * 8 + 4];
            #pragma unroll
            for (int j = 0; j < 8; j++) {
                acc[0][j] += u0 * w[j];
                acc[1][j] += u1 * w[j];
            }
        }
    }
    #pragma unroll
    for (int i = 0; i < 2; i++) {
        float o[8];
        #pragma unroll
        for (int j = 0; j < 8; j++) o[j] = fmaxf(acc[i][j], 0.f);
        *(float4*)&ts[(2 * ny + i) * 132 + tx * 8]     = *(float4*)&o[0];
        *(float4*)&ts[(2 * ny + i) * 132 + tx * 8 + 4] = *(float4*)&o[4];
    }
    __syncthreads();

    float acc2[2][8];
    #pragma unroll
    for (int i = 0; i < 2; i++)
        #pragma unroll
        for (int j = 0; j < 8; j++)
            acc2[i][j] = nb2[tx * 8 + j];
    #pragma unroll 4
    for (int k = 0; k < 128; k++) {
        float u0 = ts[(2 * ny + 0) * 132 + k];
        float u1 = ts[(2 * ny + 1) * 132 + k];
        float w[8];
        *(float4*)&w[0] = *(float4*)&nw2s[k * 128 + tx * 8];
        *(float4*)&w[4] = *(float4*)&nw2s[k * 128 + tx * 8 + 4];
        #pragma unroll
        for (int j = 0; j < 8; j++) {
            acc2[0][j] += u0 * w[j];
            acc2[1][j] += u1 * w[j];
        }
    }
    #pragma unroll
    for (int i = 0; i < 2; i++) {
        float4 o0 = make_float4(acc2[i][0], acc2[i][1], acc2[i][2], acc2[i][3]);
        float4 o1 = make_float4(acc2[i][4], acc2[i][5], acc2[i][6], acc2[i][7]);
        *(float4*)&out[(size_t)(n0 + 2 * ny + i) * H + tx * 8]     = o0;
        *(float4*)&out[(size_t)(n0 + 2 * ny + i) * H + tx * 8 + 4] = o1;
    }
}

// =====================================================================
// launch
// =====================================================================
extern "C" void kernel_launch(void* const* d_in, const int* in_sizes, int n_in,
                              void* d_out, int out_size)
{
    const float* h    = (const float*)d_in[0];
    const float* x    = (const float*)d_in[1];
    const float* ea   = (const float*)d_in[2];
    const float* ew1  = (const float*)d_in[3];
    const float* eb1  = (const float*)d_in[4];
    const float* ew2  = (const float*)d_in[5];
    const float* eb2  = (const float*)d_in[6];
    const float* infw = (const float*)d_in[7];
    const float* infb = (const float*)d_in[8];
    const float* nw1  = (const float*)d_in[9];
    const float* nb1  = (const float*)d_in[10];
    const float* nw2  = (const float*)d_in[11];
    const float* nb2  = (const float*)d_in[12];
    const float* xw1  = (const float*)d_in[13];
    const float* xb1  = (const float*)d_in[14];
    const float* xw2  = (const float*)d_in[15];
    const float* xb2  = (const float*)d_in[16];
    const int*   ei   = (const int*)d_in[17];
    float* out = (float*)d_out;

    const int EDGE_SMEM = 56704 * 4;   // 226816 bytes
    const int POST_SMEM = 37120 * 4;   // 148480 bytes
    cudaFuncSetAttribute(k_edge, cudaFuncAttributeMaxDynamicSharedMemorySize, EDGE_SMEM);
    cudaFuncSetAttribute(k_post, cudaFuncAttributeMaxDynamicSharedMemorySize, POST_SMEM);

    k_pre<<<625, 256>>>(h, ew1, eb1);
    k_edge<<<148, 256, EDGE_SMEM>>>(x, ea, ew1, ew2, eb2, infw, infb,
                                    xw1, xb1, xw2, xb2, ei);
    k_post<<<625, 256, POST_SMEM>>>(h, x, nw1, nb1, nw2, nb2, out);
}